// round 13
// baseline (speedup 1.0000x reference)
#include <cuda_runtime.h>
#include <cuda_fp16.h>
#include <cstdint>

#define HID   1024
#define HEADS 16
#define DK    64
#define BATCH 2
#define SEQ   2048
#define TOK   (BATCH * SEQ)
#define QK_SCALE_L2E 0.18033688011112042f   // 0.125 * log2(e)

// ---------------- scratch ---------------------------------------------------
__device__ __half g_W16[4][HID * HID];
__device__ __half g_X16[3][TOK * HID];
__device__ __half g_Qh[TOK * HID];        // [b,h,s,d], pre-scaled by 0.125*log2e
__device__ __half g_Kh[TOK * HID];        // [b,h,s,d]
__device__ __half g_Vt[TOK * HID];        // [b,h,d,s]
__device__ __half g_attn[TOK * HID];      // [token, h*64+d]
__device__ int    g_maskAny;

// ---------------- helpers ---------------------------------------------------
__device__ __forceinline__ uint32_t sptr(const void* p) {
    return (uint32_t)__cvta_generic_to_shared(p);
}
__device__ __forceinline__ void cp16(uint32_t s, const void* g) {
    asm volatile("cp.async.cg.shared.global [%0], [%1], 16;\n" :: "r"(s), "l"(g));
}
__device__ __forceinline__ void cp_commit() {
    asm volatile("cp.async.commit_group;\n");
}
template <int N> __device__ __forceinline__ void cp_wait() {
    asm volatile("cp.async.wait_group %0;\n" :: "n"(N));
}
__device__ __forceinline__ void mma16816(float* c, const unsigned* a,
                                         unsigned b0, unsigned b1) {
    asm volatile(
        "mma.sync.aligned.m16n8k16.row.col.f32.f16.f16.f32 "
        "{%0,%1,%2,%3}, {%4,%5,%6,%7}, {%8,%9}, {%0,%1,%2,%3};\n"
        : "+f"(c[0]), "+f"(c[1]), "+f"(c[2]), "+f"(c[3])
        : "r"(a[0]), "r"(a[1]), "r"(a[2]), "r"(a[3]), "r"(b0), "r"(b1));
}
__device__ __forceinline__ void ldsm4(unsigned* r, uint32_t addr) {
    asm volatile("ldmatrix.sync.aligned.m8n8.x4.shared.b16 {%0,%1,%2,%3}, [%4];\n"
                 : "=r"(r[0]), "=r"(r[1]), "=r"(r[2]), "=r"(r[3]) : "r"(addr));
}
__device__ __forceinline__ unsigned packh2(float x, float y) {
    __half2 h = __floats2half2_rn(x, y);
    return reinterpret_cast<unsigned&>(h);
}
__device__ __forceinline__ unsigned h2exp2_(unsigned x) {
    unsigned r; asm volatile("ex2.approx.f16x2 %0, %1;" : "=r"(r) : "r"(x)); return r;
}
// 3-input max (sm_90+ PTX), exact
__device__ __forceinline__ float fmax3(float a, float b, float c) {
    float d; asm("max.f32 %0, %1, %2, %3;" : "=f"(d) : "f"(a), "f"(b), "f"(c));
    return d;
}
// byte address of swizzled (row, half-col) in a 128B-row tile
__device__ __forceinline__ uint32_t swzb(uint32_t base, int r, int kh) {
    return base + r * 128 + ((((kh >> 3) ^ r) & 7) << 4) + ((kh & 7) << 1);
}
// hoisted-form pieces: addr = base + rb(row) + xt(kcol8)
__device__ __forceinline__ int swz_xt(int lane_r7, int kk, int kofs8) {
    return ((((kk * 2 + kofs8) ^ lane_r7) & 7) << 4);
}

// ---------------- prep: fp32 -> fp16 (16 slices) + mask reduce (2 slices) ----
__global__ void cvt18(const float* __restrict__ q, const float* __restrict__ k,
                      const float* __restrict__ v, const float* __restrict__ wq,
                      const float* __restrict__ wk, const float* __restrict__ wv,
                      const float* __restrict__ wo, const uint4* __restrict__ m) {
    if (blockIdx.x == 0 && blockIdx.y == 0 && threadIdx.x == 0) g_maskAny = 0;
    int y = blockIdx.y;
    int i = blockIdx.x * blockDim.x + threadIdx.x;   // 0 .. 262143
    if (y >= 16) {
        int seg = y - 16;
        uint4 t0 = m[(size_t)seg * 262144 + i];
        if (t0.x | t0.y | t0.z | t0.w) atomicOr(&g_maskAny, 1);
        return;
    }
    const float* src;
    __half* dst;
    size_t idx;
    if (y < 4) {
        src = (y == 0) ? wq : (y == 1) ? wk : (y == 2) ? wv : wo;
        dst = g_W16[y];
        idx = i;
    } else {
        int a = (y - 4) >> 2, seg = (y - 4) & 3;
        src = (a == 0) ? q : (a == 1) ? k : v;
        dst = g_X16[a];
        idx = (size_t)seg * 262144 + i;
    }
    float4 t = ((const float4*)src)[idx];
    __half2* d2 = (__half2*)&dst[idx * 4];
    d2[0] = __floats2half2_rn(t.x, t.y);
    d2[1] = __floats2half2_rn(t.z, t.w);
}

// ---------------- GEMM 128x128x64, 3-stage cp.async, frag double-buffer -----
__global__ __launch_bounds__(256, 2) void gemm128(int base_mode, float* __restrict__ out) {
    extern __shared__ __half sm[];
    int mode = base_mode + blockIdx.z;
    const __half* A = (mode == 0) ? g_X16[0] : (mode == 1) ? g_X16[1]
                    : (mode == 2) ? g_X16[2] : g_attn;
    const __half* W = g_W16[mode];

    int tid = threadIdx.x, lane = tid & 31, wid = tid >> 5;
    int g = lane >> 2, tg = lane & 3;
    int wm = wid & 1, wn = wid >> 1;            // 2 (m) x 4 (n) warps, 64x32 each
    int rowB = blockIdx.y * 128, colB = blockIdx.x * 128;

    int aro = lane & 15,                       ako8 = (lane >> 4);
    int bro = ((lane >> 4) << 3) + (lane & 7), bko8 = ((lane >> 3) & 1);
    uint32_t smb = sptr(sm);

    int arb[4], axt[4], brb[2], bxt[4];
#pragma unroll
    for (int mi = 0; mi < 4; mi++) arb[mi] = (wm * 64 + mi * 16 + aro) * 128;
#pragma unroll
    for (int np = 0; np < 2; np++) brb[np] = (wn * 32 + np * 16 + bro) * 128;
#pragma unroll
    for (int kk = 0; kk < 4; kk++) {
        axt[kk] = swz_xt(aro & 7, kk, ako8);
        bxt[kk] = swz_xt(bro & 7, kk, bko8);
    }

    float acc[4][4][4] = {};

    auto load_stage = [&](int kb, int st) {
        uint32_t as = smb + st * 32768;
        uint32_t bs = as + 16384;
        const __half* Ag = A + (size_t)rowB * HID + kb * 64;
        const __half* Bg = W + (size_t)colB * HID + kb * 64;
#pragma unroll
        for (int i = 0; i < 4; i++) {
            int cid = tid + i * 256;
            int r = cid >> 3, c = cid & 7;
            uint32_t so = r * 128 + ((c ^ (r & 7)) << 4);
            cp16(as + so, Ag + (size_t)r * HID + c * 8);
            cp16(bs + so, Bg + (size_t)r * HID + c * 8);
        }
        cp_commit();
    };

    load_stage(0, 0);
    load_stage(1, 1);

    unsigned af[2][4][4], bf[2][2][4];

    for (int kb = 0; kb < HID / 64; kb++) {
        cp_wait<1>(); __syncthreads();
        if (kb + 2 < HID / 64) load_stage(kb + 2, (kb + 2) % 3);
        uint32_t as = smb + (kb % 3) * 32768;
        uint32_t bs = as + 16384;

#pragma unroll
        for (int mi = 0; mi < 4; mi++) ldsm4(af[0][mi], as + arb[mi] + axt[0]);
#pragma unroll
        for (int np = 0; np < 2; np++) ldsm4(bf[0][np], bs + brb[np] + bxt[0]);

#pragma unroll
        for (int kk = 0; kk < 4; kk++) {
            int cur = kk & 1, nxt = cur ^ 1;
            if (kk < 3) {
#pragma unroll
                for (int mi = 0; mi < 4; mi++)
                    ldsm4(af[nxt][mi], as + arb[mi] + axt[kk + 1]);
#pragma unroll
                for (int np = 0; np < 2; np++)
                    ldsm4(bf[nxt][np], bs + brb[np] + bxt[kk + 1]);
            }
#pragma unroll
            for (int np = 0; np < 2; np++)
#pragma unroll
                for (int mi = 0; mi < 4; mi++) {
                    mma16816(acc[mi][np * 2],     af[cur][mi], bf[cur][np][0], bf[cur][np][1]);
                    mma16816(acc[mi][np * 2 + 1], af[cur][mi], bf[cur][np][2], bf[cur][np][3]);
                }
        }
    }

    if (mode == 3) {
#pragma unroll
        for (int mi = 0; mi < 4; mi++)
#pragma unroll
            for (int nj = 0; nj < 4; nj++) {
                int r0 = rowB + wm * 64 + mi * 16 + g;
                int c0 = colB + wn * 32 + nj * 8 + tg * 2;
                *(float2*)(out + (size_t)r0 * HID + c0) =
                    make_float2(acc[mi][nj][0], acc[mi][nj][1]);
                *(float2*)(out + (size_t)(r0 + 8) * HID + c0) =
                    make_float2(acc[mi][nj][2], acc[mi][nj][3]);
            }
    } else {
        float scale = (mode == 0) ? QK_SCALE_L2E : 1.0f;
        __half* dst = (mode == 0) ? g_Qh : (mode == 1) ? g_Kh : g_Vt;
#pragma unroll
        for (int mi = 0; mi < 4; mi++)
#pragma unroll
            for (int nj = 0; nj < 4; nj++) {
                int r0 = rowB + wm * 64 + mi * 16 + g;
                int c0 = colB + wn * 32 + nj * 8 + tg * 2;
                int b = r0 >> 11, s = r0 & (SEQ - 1);
                int h = c0 >> 6, d = c0 & 63;
                int bh = b * HEADS + h;
                if (mode == 2) {
                    size_t base = ((size_t)bh * DK + d) * SEQ + s;
                    dst[base]           = __float2half_rn(acc[mi][nj][0]);
                    dst[base + SEQ]     = __float2half_rn(acc[mi][nj][1]);
                    dst[base + 8]       = __float2half_rn(acc[mi][nj][2]);
                    dst[base + SEQ + 8] = __float2half_rn(acc[mi][nj][3]);
                } else {
                    size_t base = ((size_t)bh * SEQ + s) * DK + d;
                    *(__half2*)(dst + base) =
                        __floats2half2_rn(acc[mi][nj][0] * scale, acc[mi][nj][1] * scale);
                    *(__half2*)(dst + base + 8 * DK) =
                        __floats2half2_rn(acc[mi][nj][2] * scale, acc[mi][nj][3] * scale);
                }
            }
    }
}

// ---------------- flash attention: deferred-PV software pipeline -------------
// PV(it-1) issued alongside softmax(it): the serial max/shuffle/exp chain
// interleaves with 36 independent MMAs. Bitwise-identical float sequence to
// the non-pipelined version. V ring is 4-deep (slot 3 reuses the dead Q
// staging buffer); K ring stays 3-deep. smem 56KB -> 4 CTAs/SM unchanged.
__global__ __launch_bounds__(128, 4) void flash(const unsigned char* __restrict__ mask) {
    extern __shared__ __half fsm[];
    uint32_t smbase = sptr(fsm);
    uint32_t qb = smbase;                               // Q: 8KB, becomes V slot 3

    int tid = threadIdx.x, lane = tid & 31, wid = tid >> 5;
    int g = lane >> 2, tg = lane & 3;
    int bh = blockIdx.y, b = bh >> 4, h = bh & 15;
    int qt = blockIdx.x;

    const __half* Qp = g_Qh + (size_t)bh * SEQ * DK + (size_t)qt * 64 * DK;
    const __half* Kp = g_Kh + (size_t)bh * SEQ * DK;
    const __half* Vp = g_Vt + (size_t)bh * DK * SEQ;
    const unsigned char* Mp = mask + (size_t)b * SEQ * SEQ + (size_t)(qt * 64) * SEQ;
    int anyMask = g_maskAny;

    int aro = lane & 15,                       ako8 = (lane >> 4);
    int bro = ((lane >> 4) << 3) + (lane & 7), bko8 = ((lane >> 3) & 1);

    int rb[4], xt[4];
#pragma unroll
    for (int np = 0; np < 4; np++) rb[np] = (np * 16 + bro) * 128;
#pragma unroll
    for (int kk = 0; kk < 4; kk++) xt[kk] = swz_xt(bro & 7, kk, bko8);

    // K slots: [8K,32K) 3-deep; V slots: [32K,56K) + Q buffer as slot 3
    auto kslot = [&](int it) { return smbase + 8192 + (it % 3) * 8192; };
    auto vslot = [&](int it) {
        int s4 = it & 3;
        return (s4 == 3) ? qb : smbase + 32768 + s4 * 8192;
    };
    auto load_kv = [&](int it) {
        uint32_t kb = kslot(it), vb = vslot(it);
#pragma unroll
        for (int i = 0; i < 4; i++) {
            int cid = tid + i * 128, r = cid >> 3, c = cid & 7;
            uint32_t so = r * 128 + ((c ^ (r & 7)) << 4);
            cp16(kb + so, Kp + (size_t)it * 4096 + cid * 8);
            cp16(vb + so, Vp + (size_t)r * SEQ + it * 64 + c * 8);
        }
        cp_commit();
    };

    // prologue: {Q + KV0} group, then {KV1} group
#pragma unroll
    for (int i = 0; i < 4; i++) {
        int cid = tid + i * 128, r = cid >> 3, c = cid & 7;
        cp16(qb + r * 128 + ((c ^ (r & 7)) << 4), Qp + cid * 8);
    }
    load_kv(0);
    load_kv(1);

    cp_wait<1>(); __syncthreads();      // Q + KV0 ready

    unsigned qf[4][4];
#pragma unroll
    for (int kk = 0; kk < 4; kk++)
        ldsm4(qf[kk], swzb(qb, wid * 16 + aro, kk * 16 + ako8 * 8));

    float o[8][4] = {};
    float lacc[4] = {};
    float m0 = -1e30f, m1 = -1e30f;
    unsigned pf[4][4];
    const unsigned ONES = 0x3C003C00u;

    for (int it = 0; it < SEQ / 64; it++) {
        if (it > 0) { cp_wait<1>(); __syncthreads(); }
        if (it + 2 < SEQ / 64) load_kv(it + 2);   // K->(it+2)%3, V->(it+2)&3: no live conflict
        uint32_t kb = kslot(it);

        // S = Q K^T  (exp2 domain: Q pre-scaled by 0.125*log2e)
        float s[8][4] = {};
#pragma unroll
        for (int kk = 0; kk < 4; kk++)
#pragma unroll
            for (int np = 0; np < 4; np++) {
                unsigned bf[4];
                ldsm4(bf, kb + rb[np] + xt[kk]);
                mma16816(s[np * 2],     qf[kk], bf[0], bf[1]);
                mma16816(s[np * 2 + 1], qf[kk], bf[2], bf[3]);
            }

        if (anyMask) {
            int r0 = wid * 16 + g;
            const unsigned char* M0 = Mp + (size_t)r0 * SEQ + it * 64;
            const unsigned char* M1 = M0 + 8 * SEQ;
#pragma unroll
            for (int j = 0; j < 8; j++) {
                int c = j * 8 + tg * 2;
                if (M0[c])     s[j][0] = -1e9f;
                if (M0[c + 1]) s[j][1] = -1e9f;
                if (M1[c])     s[j][2] = -1e9f;
                if (M1[c + 1]) s[j][3] = -1e9f;
            }
        }

        // deferred PV(it-1) + lacc MMA: independent of the softmax ALU below,
        // so the scheduler hides the max/shuffle/exp chain under these MMAs
        if (it > 0) {
            uint32_t vb = vslot(it - 1);
#pragma unroll
            for (int t = 0; t < 4; t++)
#pragma unroll
                for (int np = 0; np < 4; np++) {
                    unsigned bf[4];
                    ldsm4(bf, vb + rb[np] + xt[t]);
                    mma16816(o[np * 2],     pf[t], bf[0], bf[1]);
                    mma16816(o[np * 2 + 1], pf[t], bf[2], bf[3]);
                }
#pragma unroll
            for (int t = 0; t < 4; t++)
                mma16816(lacc, pf[t], ONES, ONES);
        }

        // online softmax (log2 domain) — in-thread max3 tree + 2 shuffles (exact)
        float rm0, rm1;
        {
            float t0 = fmax3(s[0][0], s[0][1], s[1][0]);
            float t1 = fmax3(s[1][1], s[2][0], s[2][1]);
            float t2 = fmax3(s[3][0], s[3][1], s[4][0]);
            float t3 = fmax3(s[4][1], s[5][0], s[5][1]);
            float t4 = fmax3(s[6][0], s[6][1], s[7][0]);
            rm0 = fmax3(fmax3(t0, t1, t2), fmax3(t3, t4, s[7][1]), -1e30f);
            float u0 = fmax3(s[0][2], s[0][3], s[1][2]);
            float u1 = fmax3(s[1][3], s[2][2], s[2][3]);
            float u2 = fmax3(s[3][2], s[3][3], s[4][2]);
            float u3 = fmax3(s[4][3], s[5][2], s[5][3]);
            float u4 = fmax3(s[6][2], s[6][3], s[7][2]);
            rm1 = fmax3(fmax3(u0, u1, u2), fmax3(u3, u4, s[7][3]), -1e30f);
        }
        rm0 = fmaxf(rm0, __shfl_xor_sync(0xffffffffu, rm0, 1));
        rm0 = fmaxf(rm0, __shfl_xor_sync(0xffffffffu, rm0, 2));
        rm1 = fmaxf(rm1, __shfl_xor_sync(0xffffffffu, rm1, 1));
        rm1 = fmaxf(rm1, __shfl_xor_sync(0xffffffffu, rm1, 2));
        float nm0 = fmaxf(m0, rm0), nm1 = fmaxf(m1, rm1);
        float a0 = exp2f(m0 - nm0), a1 = exp2f(m1 - nm1);
        m0 = nm0; m1 = nm1;
        // rescale AFTER PV(it-1) has accumulated (same float sequence as before)
        if (!__all_sync(0xffffffffu, (a0 == 1.0f) & (a1 == 1.0f))) {
#pragma unroll
            for (int j = 0; j < 8; j++) {
                o[j][0] *= a0; o[j][1] *= a0;
                o[j][2] *= a1; o[j][3] *= a1;
            }
            lacc[0] *= a0; lacc[1] *= a0; lacc[2] *= a1; lacc[3] *= a1;
        }

        // new P fragments (consumed next iteration / drain)
#pragma unroll
        for (int t = 0; t < 4; t++) {
            pf[t][0] = h2exp2_(packh2(s[2*t][0]   - nm0, s[2*t][1]   - nm0));
            pf[t][1] = h2exp2_(packh2(s[2*t][2]   - nm1, s[2*t][3]   - nm1));
            pf[t][2] = h2exp2_(packh2(s[2*t+1][0] - nm0, s[2*t+1][1] - nm0));
            pf[t][3] = h2exp2_(packh2(s[2*t+1][2] - nm1, s[2*t+1][3] - nm1));
        }
    }

    // drain: PV of the last tile
    {
        uint32_t vb = vslot(SEQ / 64 - 1);
#pragma unroll
        for (int t = 0; t < 4; t++)
#pragma unroll
            for (int np = 0; np < 4; np++) {
                unsigned bf[4];
                ldsm4(bf, vb + rb[np] + xt[t]);
                mma16816(o[np * 2],     pf[t], bf[0], bf[1]);
                mma16816(o[np * 2 + 1], pf[t], bf[2], bf[3]);
            }
#pragma unroll
        for (int t = 0; t < 4; t++)
            mma16816(lacc, pf[t], ONES, ONES);
    }

    float inv0 = 1.f / lacc[0], inv1 = 1.f / lacc[2];
    int srow = qt * 64 + wid * 16 + g;
#pragma unroll
    for (int j = 0; j < 8; j++) {
        int c = h * 64 + j * 8 + tg * 2;
        *(__half2*)(g_attn + (size_t)(b * SEQ + srow) * HID + c) =
            __floats2half2_rn(o[j][0] * inv0, o[j][1] * inv0);
        *(__half2*)(g_attn + (size_t)(b * SEQ + srow + 8) * HID + c) =
            __floats2half2_rn(o[j][2] * inv1, o[j][3] * inv1);
    }
}

// ---------------- launch -----------------------------------------------------
extern "C" void kernel_launch(void* const* d_in, const int* in_sizes, int n_in,
                              void* d_out, int out_size) {
    (void)in_sizes; (void)n_in; (void)out_size;
    const float* q = (const float*)d_in[0];
    const float* k = (const float*)d_in[1];
    const float* v = (const float*)d_in[2];
    const unsigned char* mask = (const unsigned char*)d_in[3];
    const float* Wq = (const float*)d_in[4];
    const float* Wk = (const float*)d_in[5];
    const float* Wv = (const float*)d_in[6];
    const float* Wo = (const float*)d_in[7];
    float* out = (float*)d_out;

    const int GSM = 3 * 32768;          // 96 KB
    const int FSM = 8192 + 3 * 8192 + 3 * 8192;   // 56 KB -> 4 CTAs/SM
    static bool done = false;
    if (!done) {
        cudaFuncSetAttribute(gemm128, cudaFuncAttributeMaxDynamicSharedMemorySize, GSM);
        cudaFuncSetAttribute(flash,   cudaFuncAttributeMaxDynamicSharedMemorySize, FSM);
        done = true;
    }

    cvt18<<<dim3(1024, 18), 256>>>(q, k, v, Wq, Wk, Wv, Wo, (const uint4*)mask);

    gemm128<<<dim3(8, 32, 3), 256, GSM>>>(0, nullptr);   // fused Q,K,V projections

    flash<<<dim3(SEQ / 64, BATCH * HEADS), 128, FSM>>>(mask);

    gemm128<<<dim3(8, 32, 1), 256, GSM>>>(3, out);       // output projection
}

// round 14
// speedup vs baseline: 1.0426x; 1.0426x over previous
#include <cuda_runtime.h>
#include <cuda_fp16.h>
#include <cstdint>

#define HID   1024
#define HEADS 16
#define DK    64
#define BATCH 2
#define SEQ   2048
#define TOK   (BATCH * SEQ)
#define QK_SCALE_L2E 0.18033688011112042f   // 0.125 * log2(e)

// ---------------- scratch ---------------------------------------------------
__device__ __half g_W16[4][HID * HID];
__device__ __half g_X16[3][TOK * HID];
__device__ __half g_Qh[TOK * HID];        // [b,h,s,d], pre-scaled by 0.125*log2e
__device__ __half g_Kh[TOK * HID];        // [b,h,s,d]
__device__ __half g_Vt[TOK * HID];        // [b,h,d,s]
__device__ __half g_attn[TOK * HID];      // [token, h*64+d]
__device__ int    g_maskAny;

// ---------------- helpers ---------------------------------------------------
__device__ __forceinline__ uint32_t sptr(const void* p) {
    return (uint32_t)__cvta_generic_to_shared(p);
}
__device__ __forceinline__ void cp16(uint32_t s, const void* g) {
    asm volatile("cp.async.cg.shared.global [%0], [%1], 16;\n" :: "r"(s), "l"(g));
}
__device__ __forceinline__ void cp_commit() {
    asm volatile("cp.async.commit_group;\n");
}
template <int N> __device__ __forceinline__ void cp_wait() {
    asm volatile("cp.async.wait_group %0;\n" :: "n"(N));
}
__device__ __forceinline__ void mma16816(float* c, const unsigned* a,
                                         unsigned b0, unsigned b1) {
    asm volatile(
        "mma.sync.aligned.m16n8k16.row.col.f32.f16.f16.f32 "
        "{%0,%1,%2,%3}, {%4,%5,%6,%7}, {%8,%9}, {%0,%1,%2,%3};\n"
        : "+f"(c[0]), "+f"(c[1]), "+f"(c[2]), "+f"(c[3])
        : "r"(a[0]), "r"(a[1]), "r"(a[2]), "r"(a[3]), "r"(b0), "r"(b1));
}
__device__ __forceinline__ void ldsm4(unsigned* r, uint32_t addr) {
    asm volatile("ldmatrix.sync.aligned.m8n8.x4.shared.b16 {%0,%1,%2,%3}, [%4];\n"
                 : "=r"(r[0]), "=r"(r[1]), "=r"(r[2]), "=r"(r[3]) : "r"(addr));
}
__device__ __forceinline__ unsigned packh2(float x, float y) {
    __half2 h = __floats2half2_rn(x, y);
    return reinterpret_cast<unsigned&>(h);
}
__device__ __forceinline__ unsigned h2exp2_(unsigned x) {
    unsigned r; asm volatile("ex2.approx.f16x2 %0, %1;" : "=r"(r) : "r"(x)); return r;
}
// 3-input max (sm_90+ PTX), exact
__device__ __forceinline__ float fmax3(float a, float b, float c) {
    float d; asm("max.f32 %0, %1, %2, %3;" : "=f"(d) : "f"(a), "f"(b), "f"(c));
    return d;
}
// byte address of swizzled (row, half-col) in a 128B-row tile
__device__ __forceinline__ uint32_t swzb(uint32_t base, int r, int kh) {
    return base + r * 128 + ((((kh >> 3) ^ r) & 7) << 4) + ((kh & 7) << 1);
}
// hoisted-form pieces: addr = base + rb(row) + xt(kcol8)
__device__ __forceinline__ int swz_xt(int lane_r7, int kk, int kofs8) {
    return ((((kk * 2 + kofs8) ^ lane_r7) & 7) << 4);
}

// ---------------- prep: fp32 -> fp16 (16 slices) + mask reduce (2 slices) ----
__global__ void cvt18(const float* __restrict__ q, const float* __restrict__ k,
                      const float* __restrict__ v, const float* __restrict__ wq,
                      const float* __restrict__ wk, const float* __restrict__ wv,
                      const float* __restrict__ wo, const uint4* __restrict__ m) {
    if (blockIdx.x == 0 && blockIdx.y == 0 && threadIdx.x == 0) g_maskAny = 0;
    int y = blockIdx.y;
    int i = blockIdx.x * blockDim.x + threadIdx.x;   // 0 .. 262143
    if (y >= 16) {
        int seg = y - 16;
        uint4 t0 = m[(size_t)seg * 262144 + i];
        if (t0.x | t0.y | t0.z | t0.w) atomicOr(&g_maskAny, 1);
        return;
    }
    const float* src;
    __half* dst;
    size_t idx;
    if (y < 4) {
        src = (y == 0) ? wq : (y == 1) ? wk : (y == 2) ? wv : wo;
        dst = g_W16[y];
        idx = i;
    } else {
        int a = (y - 4) >> 2, seg = (y - 4) & 3;
        src = (a == 0) ? q : (a == 1) ? k : v;
        dst = g_X16[a];
        idx = (size_t)seg * 262144 + i;
    }
    float4 t = ((const float4*)src)[idx];
    __half2* d2 = (__half2*)&dst[idx * 4];
    d2[0] = __floats2half2_rn(t.x, t.y);
    d2[1] = __floats2half2_rn(t.z, t.w);
}

// ---------------- GEMM 128x128x64, 3-stage cp.async, frag double-buffer -----
__global__ __launch_bounds__(256, 2) void gemm128(int base_mode, float* __restrict__ out) {
    extern __shared__ __half sm[];
    int mode = base_mode + blockIdx.z;
    const __half* A = (mode == 0) ? g_X16[0] : (mode == 1) ? g_X16[1]
                    : (mode == 2) ? g_X16[2] : g_attn;
    const __half* W = g_W16[mode];

    int tid = threadIdx.x, lane = tid & 31, wid = tid >> 5;
    int g = lane >> 2, tg = lane & 3;
    int wm = wid & 1, wn = wid >> 1;            // 2 (m) x 4 (n) warps, 64x32 each
    int rowB = blockIdx.y * 128, colB = blockIdx.x * 128;

    int aro = lane & 15,                       ako8 = (lane >> 4);
    int bro = ((lane >> 4) << 3) + (lane & 7), bko8 = ((lane >> 3) & 1);
    uint32_t smb = sptr(sm);

    int arb[4], axt[4], brb[2], bxt[4];
#pragma unroll
    for (int mi = 0; mi < 4; mi++) arb[mi] = (wm * 64 + mi * 16 + aro) * 128;
#pragma unroll
    for (int np = 0; np < 2; np++) brb[np] = (wn * 32 + np * 16 + bro) * 128;
#pragma unroll
    for (int kk = 0; kk < 4; kk++) {
        axt[kk] = swz_xt(aro & 7, kk, ako8);
        bxt[kk] = swz_xt(bro & 7, kk, bko8);
    }

    float acc[4][4][4] = {};

    auto load_stage = [&](int kb, int st) {
        uint32_t as = smb + st * 32768;
        uint32_t bs = as + 16384;
        const __half* Ag = A + (size_t)rowB * HID + kb * 64;
        const __half* Bg = W + (size_t)colB * HID + kb * 64;
#pragma unroll
        for (int i = 0; i < 4; i++) {
            int cid = tid + i * 256;
            int r = cid >> 3, c = cid & 7;
            uint32_t so = r * 128 + ((c ^ (r & 7)) << 4);
            cp16(as + so, Ag + (size_t)r * HID + c * 8);
            cp16(bs + so, Bg + (size_t)r * HID + c * 8);
        }
        cp_commit();
    };

    load_stage(0, 0);
    load_stage(1, 1);

    unsigned af[2][4][4], bf[2][2][4];

    for (int kb = 0; kb < HID / 64; kb++) {
        cp_wait<1>(); __syncthreads();
        if (kb + 2 < HID / 64) load_stage(kb + 2, (kb + 2) % 3);
        uint32_t as = smb + (kb % 3) * 32768;
        uint32_t bs = as + 16384;

#pragma unroll
        for (int mi = 0; mi < 4; mi++) ldsm4(af[0][mi], as + arb[mi] + axt[0]);
#pragma unroll
        for (int np = 0; np < 2; np++) ldsm4(bf[0][np], bs + brb[np] + bxt[0]);

#pragma unroll
        for (int kk = 0; kk < 4; kk++) {
            int cur = kk & 1, nxt = cur ^ 1;
            if (kk < 3) {
#pragma unroll
                for (int mi = 0; mi < 4; mi++)
                    ldsm4(af[nxt][mi], as + arb[mi] + axt[kk + 1]);
#pragma unroll
                for (int np = 0; np < 2; np++)
                    ldsm4(bf[nxt][np], bs + brb[np] + bxt[kk + 1]);
            }
#pragma unroll
            for (int np = 0; np < 2; np++)
#pragma unroll
                for (int mi = 0; mi < 4; mi++) {
                    mma16816(acc[mi][np * 2],     af[cur][mi], bf[cur][np][0], bf[cur][np][1]);
                    mma16816(acc[mi][np * 2 + 1], af[cur][mi], bf[cur][np][2], bf[cur][np][3]);
                }
        }
    }

    if (mode == 3) {
#pragma unroll
        for (int mi = 0; mi < 4; mi++)
#pragma unroll
            for (int nj = 0; nj < 4; nj++) {
                int r0 = rowB + wm * 64 + mi * 16 + g;
                int c0 = colB + wn * 32 + nj * 8 + tg * 2;
                *(float2*)(out + (size_t)r0 * HID + c0) =
                    make_float2(acc[mi][nj][0], acc[mi][nj][1]);
                *(float2*)(out + (size_t)(r0 + 8) * HID + c0) =
                    make_float2(acc[mi][nj][2], acc[mi][nj][3]);
            }
    } else {
        float scale = (mode == 0) ? QK_SCALE_L2E : 1.0f;
        __half* dst = (mode == 0) ? g_Qh : (mode == 1) ? g_Kh : g_Vt;
#pragma unroll
        for (int mi = 0; mi < 4; mi++)
#pragma unroll
            for (int nj = 0; nj < 4; nj++) {
                int r0 = rowB + wm * 64 + mi * 16 + g;
                int c0 = colB + wn * 32 + nj * 8 + tg * 2;
                int b = r0 >> 11, s = r0 & (SEQ - 1);
                int h = c0 >> 6, d = c0 & 63;
                int bh = b * HEADS + h;
                if (mode == 2) {
                    size_t base = ((size_t)bh * DK + d) * SEQ + s;
                    dst[base]           = __float2half_rn(acc[mi][nj][0]);
                    dst[base + SEQ]     = __float2half_rn(acc[mi][nj][1]);
                    dst[base + 8]       = __float2half_rn(acc[mi][nj][2]);
                    dst[base + SEQ + 8] = __float2half_rn(acc[mi][nj][3]);
                } else {
                    size_t base = ((size_t)bh * SEQ + s) * DK + d;
                    *(__half2*)(dst + base) =
                        __floats2half2_rn(acc[mi][nj][0] * scale, acc[mi][nj][1] * scale);
                    *(__half2*)(dst + base + 8 * DK) =
                        __floats2half2_rn(acc[mi][nj][2] * scale, acc[mi][nj][3] * scale);
                }
            }
    }
}

// ---------------- flash attention: 64q x 64k, 4 warps, 3-stage KV ring -------
// online softmax (exact): in-thread max3 tree + 3 PARALLEL shuffles (xor 1,2,3)
__global__ __launch_bounds__(128, 4) void flash(const unsigned char* __restrict__ mask) {
    extern __shared__ __half fsm[];
    uint32_t smbase = sptr(fsm);
    uint32_t qb = smbase;                               // Q: 64x64 halves, 8KB

    int tid = threadIdx.x, lane = tid & 31, wid = tid >> 5;
    int g = lane >> 2, tg = lane & 3;
    int bh = blockIdx.y, b = bh >> 4, h = bh & 15;
    int qt = blockIdx.x;

    const __half* Qp = g_Qh + (size_t)bh * SEQ * DK + (size_t)qt * 64 * DK;
    const __half* Kp = g_Kh + (size_t)bh * SEQ * DK;
    const __half* Vp = g_Vt + (size_t)bh * DK * SEQ;
    const unsigned char* Mp = mask + (size_t)b * SEQ * SEQ + (size_t)(qt * 64) * SEQ;
    int anyMask = g_maskAny;

    int aro = lane & 15,                       ako8 = (lane >> 4);
    int bro = ((lane >> 4) << 3) + (lane & 7), bko8 = ((lane >> 3) & 1);

    int rb[4], xt[4];
#pragma unroll
    for (int np = 0; np < 4; np++) rb[np] = (np * 16 + bro) * 128;
#pragma unroll
    for (int kk = 0; kk < 4; kk++) xt[kk] = swz_xt(bro & 7, kk, bko8);

    auto kvbase = [&](int st, int kv) { return smbase + 8192 + (st * 2 + kv) * 8192; };
    auto load_kv = [&](int it, int st) {
#pragma unroll
        for (int i = 0; i < 4; i++) {
            int cid = tid + i * 128, r = cid >> 3, c = cid & 7;
            uint32_t so = r * 128 + ((c ^ (r & 7)) << 4);
            cp16(kvbase(st, 0) + so, Kp + (size_t)it * 4096 + cid * 8);
            cp16(kvbase(st, 1) + so, Vp + (size_t)r * SEQ + it * 64 + c * 8);
        }
        cp_commit();
    };

    // prologue: {Q + KV0} group, then {KV1} group
#pragma unroll
    for (int i = 0; i < 4; i++) {
        int cid = tid + i * 128, r = cid >> 3, c = cid & 7;
        cp16(qb + r * 128 + ((c ^ (r & 7)) << 4), Qp + cid * 8);
    }
    load_kv(0, 0);
    load_kv(1, 1);

    cp_wait<1>(); __syncthreads();      // Q + KV0 ready

    unsigned qf[4][4];
#pragma unroll
    for (int kk = 0; kk < 4; kk++)
        ldsm4(qf[kk], swzb(qb, wid * 16 + aro, kk * 16 + ako8 * 8));

    float o[8][4] = {};
    float lacc[4] = {};
    float m0 = -1e30f, m1 = -1e30f;
    const unsigned ONES = 0x3C003C00u;

    for (int it = 0; it < SEQ / 64; it++) {
        if (it > 0) { cp_wait<1>(); __syncthreads(); }
        if (it + 2 < SEQ / 64) load_kv(it + 2, (it + 2) % 3);
        uint32_t kb = kvbase(it % 3, 0), vb = kvbase(it % 3, 1);

        // S = Q K^T  (exp2 domain: Q pre-scaled by 0.125*log2e)
        float s[8][4] = {};
#pragma unroll
        for (int kk = 0; kk < 4; kk++)
#pragma unroll
            for (int np = 0; np < 4; np++) {
                unsigned bf[4];
                ldsm4(bf, kb + rb[np] + xt[kk]);
                mma16816(s[np * 2],     qf[kk], bf[0], bf[1]);
                mma16816(s[np * 2 + 1], qf[kk], bf[2], bf[3]);
            }

        if (anyMask) {
            int r0 = wid * 16 + g;
            const unsigned char* M0 = Mp + (size_t)r0 * SEQ + it * 64;
            const unsigned char* M1 = M0 + 8 * SEQ;
#pragma unroll
            for (int j = 0; j < 8; j++) {
                int c = j * 8 + tg * 2;
                if (M0[c])     s[j][0] = -1e9f;
                if (M0[c + 1]) s[j][1] = -1e9f;
                if (M1[c])     s[j][2] = -1e9f;
                if (M1[c + 1]) s[j][3] = -1e9f;
            }
        }

        // online softmax (log2 domain) — max3 tree + 3 parallel shuffles (exact)
        float rm0, rm1;
        {
            float t0 = fmax3(s[0][0], s[0][1], s[1][0]);
            float t1 = fmax3(s[1][1], s[2][0], s[2][1]);
            float t2 = fmax3(s[3][0], s[3][1], s[4][0]);
            float t3 = fmax3(s[4][1], s[5][0], s[5][1]);
            float t4 = fmax3(s[6][0], s[6][1], s[7][0]);
            rm0 = fmax3(fmax3(t0, t1, t2), fmax3(t3, t4, s[7][1]), -1e30f);
            float u0 = fmax3(s[0][2], s[0][3], s[1][2]);
            float u1 = fmax3(s[1][3], s[2][2], s[2][3]);
            float u2 = fmax3(s[3][2], s[3][3], s[4][2]);
            float u3 = fmax3(s[4][3], s[5][2], s[5][3]);
            float u4 = fmax3(s[6][2], s[6][3], s[7][2]);
            rm1 = fmax3(fmax3(u0, u1, u2), fmax3(u3, u4, s[7][3]), -1e30f);
        }
        {   // quad max via 3 independent shuffles (1 shuffle latency, not 2)
            float p1 = __shfl_xor_sync(0xffffffffu, rm0, 1);
            float p2 = __shfl_xor_sync(0xffffffffu, rm0, 2);
            float p3 = __shfl_xor_sync(0xffffffffu, rm0, 3);
            rm0 = fmax3(fmaxf(rm0, p1), p2, p3);
            float q1 = __shfl_xor_sync(0xffffffffu, rm1, 1);
            float q2 = __shfl_xor_sync(0xffffffffu, rm1, 2);
            float q3 = __shfl_xor_sync(0xffffffffu, rm1, 3);
            rm1 = fmax3(fmaxf(rm1, q1), q2, q3);
        }
        float nm0 = fmaxf(m0, rm0), nm1 = fmaxf(m1, rm1);
        float a0 = exp2f(m0 - nm0), a1 = exp2f(m1 - nm1);
        m0 = nm0; m1 = nm1;
        // warp-uniform skip: rescale only when some row's max moved
        if (!__all_sync(0xffffffffu, (a0 == 1.0f) & (a1 == 1.0f))) {
#pragma unroll
            for (int j = 0; j < 8; j++) {
                o[j][0] *= a0; o[j][1] *= a0;
                o[j][2] *= a1; o[j][3] *= a1;
            }
            lacc[0] *= a0; lacc[1] *= a0; lacc[2] *= a1; lacc[3] *= a1;
        }

        // P = 2^(s-nm) as fp16 fragments, straight from score regs
        unsigned pf[4][4];
#pragma unroll
        for (int t = 0; t < 4; t++) {
            pf[t][0] = h2exp2_(packh2(s[2*t][0]   - nm0, s[2*t][1]   - nm0));
            pf[t][1] = h2exp2_(packh2(s[2*t][2]   - nm1, s[2*t][3]   - nm1));
            pf[t][2] = h2exp2_(packh2(s[2*t+1][0] - nm0, s[2*t+1][1] - nm0));
            pf[t][3] = h2exp2_(packh2(s[2*t+1][2] - nm1, s[2*t+1][3] - nm1));
        }
#pragma unroll
        for (int t = 0; t < 4; t++)
            mma16816(lacc, pf[t], ONES, ONES);      // exact f32 row sums of P

        // O += P V   (V tile is [d][key] -> n=d, k=keys)
#pragma unroll
        for (int t = 0; t < 4; t++)
#pragma unroll
            for (int np = 0; np < 4; np++) {
                unsigned bf[4];
                ldsm4(bf, vb + rb[np] + xt[t]);
                mma16816(o[np * 2],     pf[t], bf[0], bf[1]);
                mma16816(o[np * 2 + 1], pf[t], bf[2], bf[3]);
            }
    }

    float inv0 = 1.f / lacc[0], inv1 = 1.f / lacc[2];
    int srow = qt * 64 + wid * 16 + g;
#pragma unroll
    for (int j = 0; j < 8; j++) {
        int c = h * 64 + j * 8 + tg * 2;
        *(__half2*)(g_attn + (size_t)(b * SEQ + srow) * HID + c) =
            __floats2half2_rn(o[j][0] * inv0, o[j][1] * inv0);
        *(__half2*)(g_attn + (size_t)(b * SEQ + srow + 8) * HID + c) =
            __floats2half2_rn(o[j][2] * inv1, o[j][3] * inv1);
    }
}

// ---------------- launch -----------------------------------------------------
extern "C" void kernel_launch(void* const* d_in, const int* in_sizes, int n_in,
                              void* d_out, int out_size) {
    (void)in_sizes; (void)n_in; (void)out_size;
    const float* q = (const float*)d_in[0];
    const float* k = (const float*)d_in[1];
    const float* v = (const float*)d_in[2];
    const unsigned char* mask = (const unsigned char*)d_in[3];
    const float* Wq = (const float*)d_in[4];
    const float* Wk = (const float*)d_in[5];
    const float* Wv = (const float*)d_in[6];
    const float* Wo = (const float*)d_in[7];
    float* out = (float*)d_out;

    const int GSM = 3 * 32768;          // 96 KB
    const int FSM = 8192 + 3 * 16384;   // 56 KB -> 4 CTAs/SM
    static bool done = false;
    if (!done) {
        cudaFuncSetAttribute(gemm128, cudaFuncAttributeMaxDynamicSharedMemorySize, GSM);
        cudaFuncSetAttribute(flash,   cudaFuncAttributeMaxDynamicSharedMemorySize, FSM);
        done = true;
    }

    cvt18<<<dim3(1024, 18), 256>>>(q, k, v, Wq, Wk, Wv, Wo, (const uint4*)mask);

    gemm128<<<dim3(8, 32, 3), 256, GSM>>>(0, nullptr);   // fused Q,K,V projections

    flash<<<dim3(SEQ / 64, BATCH * HEADS), 128, FSM>>>(mask);

    gemm128<<<dim3(8, 32, 1), 256, GSM>>>(3, out);       // output projection
}

// round 15
// speedup vs baseline: 1.0878x; 1.0434x over previous
#include <cuda_runtime.h>
#include <cuda_fp16.h>
#include <cstdint>

#define HID   1024
#define HEADS 16
#define DK    64
#define BATCH 2
#define SEQ   2048
#define TOK   (BATCH * SEQ)
#define QK_SCALE_L2E 0.18033688011112042f   // 0.125 * log2(e)

// ---------------- scratch ---------------------------------------------------
__device__ __half g_W16[4][HID * HID];
__device__ __half g_X16[3][TOK * HID];
__device__ __half g_Qh[TOK * HID];        // [b,h,s,d], pre-scaled by 0.125*log2e
__device__ __half g_Kh[TOK * HID];        // [b,h,s,d]
__device__ __half g_Vt[TOK * HID];        // [b,h,d,s]
__device__ __half g_attn[TOK * HID];      // [token, h*64+d]
__device__ int    g_maskAny;

// ---------------- helpers ---------------------------------------------------
__device__ __forceinline__ uint32_t sptr(const void* p) {
    return (uint32_t)__cvta_generic_to_shared(p);
}
__device__ __forceinline__ void cp16(uint32_t s, const void* g) {
    asm volatile("cp.async.cg.shared.global [%0], [%1], 16;\n" :: "r"(s), "l"(g));
}
__device__ __forceinline__ void cp_commit() {
    asm volatile("cp.async.commit_group;\n");
}
template <int N> __device__ __forceinline__ void cp_wait() {
    asm volatile("cp.async.wait_group %0;\n" :: "n"(N));
}
__device__ __forceinline__ void mma16816(float* c, const unsigned* a,
                                         unsigned b0, unsigned b1) {
    asm volatile(
        "mma.sync.aligned.m16n8k16.row.col.f32.f16.f16.f32 "
        "{%0,%1,%2,%3}, {%4,%5,%6,%7}, {%8,%9}, {%0,%1,%2,%3};\n"
        : "+f"(c[0]), "+f"(c[1]), "+f"(c[2]), "+f"(c[3])
        : "r"(a[0]), "r"(a[1]), "r"(a[2]), "r"(a[3]), "r"(b0), "r"(b1));
}
__device__ __forceinline__ void ldsm4(unsigned* r, uint32_t addr) {
    asm volatile("ldmatrix.sync.aligned.m8n8.x4.shared.b16 {%0,%1,%2,%3}, [%4];\n"
                 : "=r"(r[0]), "=r"(r[1]), "=r"(r[2]), "=r"(r[3]) : "r"(addr));
}
__device__ __forceinline__ unsigned packh2(float x, float y) {
    __half2 h = __floats2half2_rn(x, y);
    return reinterpret_cast<unsigned&>(h);
}
__device__ __forceinline__ unsigned h2exp2_(unsigned x) {
    unsigned r; asm volatile("ex2.approx.f16x2 %0, %1;" : "=r"(r) : "r"(x)); return r;
}
// 3-input max (sm_90+ PTX), exact
__device__ __forceinline__ float fmax3(float a, float b, float c) {
    float d; asm("max.f32 %0, %1, %2, %3;" : "=f"(d) : "f"(a), "f"(b), "f"(c));
    return d;
}
// byte address of swizzled (row, half-col) in a 128B-row tile
__device__ __forceinline__ uint32_t swzb(uint32_t base, int r, int kh) {
    return base + r * 128 + ((((kh >> 3) ^ r) & 7) << 4) + ((kh & 7) << 1);
}
// hoisted-form pieces: addr = base + rb(row) + xt(kcol8)
__device__ __forceinline__ int swz_xt(int lane_r7, int kk, int kofs8) {
    return ((((kk * 2 + kofs8) ^ lane_r7) & 7) << 4);
}

// ---------------- prep: fp32 -> fp16 (16 slices) + mask reduce (2 slices) ----
__global__ void cvt18(const float* __restrict__ q, const float* __restrict__ k,
                      const float* __restrict__ v, const float* __restrict__ wq,
                      const float* __restrict__ wk, const float* __restrict__ wv,
                      const float* __restrict__ wo, const uint4* __restrict__ m) {
    if (blockIdx.x == 0 && blockIdx.y == 0 && threadIdx.x == 0) g_maskAny = 0;
    int y = blockIdx.y;
    int i = blockIdx.x * blockDim.x + threadIdx.x;   // 0 .. 262143
    if (y >= 16) {
        int seg = y - 16;
        uint4 t0 = m[(size_t)seg * 262144 + i];
        if (t0.x | t0.y | t0.z | t0.w) atomicOr(&g_maskAny, 1);
        return;
    }
    const float* src;
    __half* dst;
    size_t idx;
    if (y < 4) {
        src = (y == 0) ? wq : (y == 1) ? wk : (y == 2) ? wv : wo;
        dst = g_W16[y];
        idx = i;
    } else {
        int a = (y - 4) >> 2, seg = (y - 4) & 3;
        src = (a == 0) ? q : (a == 1) ? k : v;
        dst = g_X16[a];
        idx = (size_t)seg * 262144 + i;
    }
    float4 t = ((const float4*)src)[idx];
    __half2* d2 = (__half2*)&dst[idx * 4];
    d2[0] = __floats2half2_rn(t.x, t.y);
    d2[1] = __floats2half2_rn(t.z, t.w);
}

// ---------------- GEMM 64x128x64, 4 warps, 2-stage, 4 CTAs/SM ---------------
// Flash-shaped: small barrier domain (4 warps), 4 independent CTAs/SM, full RF.
// Warp-tile 16x128 (64 acc regs). W tiles stay L2-resident.
__global__ __launch_bounds__(128, 4) void gemm64(int base_mode, float* __restrict__ out) {
    extern __shared__ __half sm[];      // 2 stages * (A 8KB + B 16KB)
    int mode = base_mode + blockIdx.z;
    const __half* A = (mode == 0) ? g_X16[0] : (mode == 1) ? g_X16[1]
                    : (mode == 2) ? g_X16[2] : g_attn;
    const __half* W = g_W16[mode];

    int tid = threadIdx.x, lane = tid & 31, wid = tid >> 5;
    int g = lane >> 2, tg = lane & 3;
    int rowB = blockIdx.y * 64, colB = blockIdx.x * 128;

    int aro = lane & 15,                       ako8 = (lane >> 4);
    int bro = ((lane >> 4) << 3) + (lane & 7), bko8 = ((lane >> 3) & 1);
    uint32_t smb = sptr(sm);

    int arb = (wid * 16 + aro) * 128;
    int axt[4], bxt[4], rb[8];
#pragma unroll
    for (int kk = 0; kk < 4; kk++) {
        axt[kk] = swz_xt(aro & 7, kk, ako8);
        bxt[kk] = swz_xt(bro & 7, kk, bko8);
    }
#pragma unroll
    for (int np = 0; np < 8; np++) rb[np] = (np * 16 + bro) * 128;

    float acc[16][4] = {};

    auto load_stage = [&](int kb, int st) {
        uint32_t as = smb + st * 24576;
        uint32_t bs = as + 8192;
        const __half* Ag = A + (size_t)rowB * HID + kb * 64;
        const __half* Bg = W + (size_t)colB * HID + kb * 64;
#pragma unroll
        for (int i = 0; i < 4; i++) {           // A: 64x64 -> 512 chunks
            int cid = tid + i * 128;
            int r = cid >> 3, c = cid & 7;
            cp16(as + r * 128 + ((c ^ (r & 7)) << 4), Ag + (size_t)r * HID + c * 8);
        }
#pragma unroll
        for (int i = 0; i < 8; i++) {           // B: 128x64 -> 1024 chunks
            int cid = tid + i * 128;
            int r = cid >> 3, c = cid & 7;
            cp16(bs + r * 128 + ((c ^ (r & 7)) << 4), Bg + (size_t)r * HID + c * 8);
        }
        cp_commit();
    };

    load_stage(0, 0);

    for (int kb = 0; kb < HID / 64; kb++) {
        cp_wait<0>(); __syncthreads();
        if (kb + 1 < HID / 64) load_stage(kb + 1, (kb + 1) & 1);
        uint32_t as = smb + (kb & 1) * 24576;
        uint32_t bs = as + 8192;
#pragma unroll
        for (int kk = 0; kk < 4; kk++) {
            unsigned af[4];
            ldsm4(af, as + arb + axt[kk]);
#pragma unroll
            for (int np = 0; np < 8; np++) {
                unsigned bf[4];
                ldsm4(bf, bs + rb[np] + bxt[kk]);
                mma16816(acc[np * 2],     af, bf[0], bf[1]);
                mma16816(acc[np * 2 + 1], af, bf[2], bf[3]);
            }
        }
        __syncthreads();
    }

    int r0 = rowB + wid * 16 + g;
    if (mode == 3) {
#pragma unroll
        for (int nj = 0; nj < 16; nj++) {
            int c0 = colB + nj * 8 + tg * 2;
            *(float2*)(out + (size_t)r0 * HID + c0) =
                make_float2(acc[nj][0], acc[nj][1]);
            *(float2*)(out + (size_t)(r0 + 8) * HID + c0) =
                make_float2(acc[nj][2], acc[nj][3]);
        }
    } else {
        float scale = (mode == 0) ? QK_SCALE_L2E : 1.0f;
        __half* dst = (mode == 0) ? g_Qh : (mode == 1) ? g_Kh : g_Vt;
        int b = r0 >> 11, s = r0 & (SEQ - 1);
#pragma unroll
        for (int nj = 0; nj < 16; nj++) {
            int c0 = colB + nj * 8 + tg * 2;
            int h = c0 >> 6, d = c0 & 63;
            int bh = b * HEADS + h;
            if (mode == 2) {
                size_t base = ((size_t)bh * DK + d) * SEQ + s;
                dst[base]           = __float2half_rn(acc[nj][0]);
                dst[base + SEQ]     = __float2half_rn(acc[nj][1]);
                dst[base + 8]       = __float2half_rn(acc[nj][2]);
                dst[base + SEQ + 8] = __float2half_rn(acc[nj][3]);
            } else {
                size_t base = ((size_t)bh * SEQ + s) * DK + d;
                *(__half2*)(dst + base) =
                    __floats2half2_rn(acc[nj][0] * scale, acc[nj][1] * scale);
                *(__half2*)(dst + base + 8 * DK) =
                    __floats2half2_rn(acc[nj][2] * scale, acc[nj][3] * scale);
            }
        }
    }
}

// ---------------- flash attention: 64q x 64k, 4 warps, 3-stage KV ring -------
// online softmax (exact): in-thread max3 tree + two butterfly shuffles
__global__ __launch_bounds__(128, 4) void flash(const unsigned char* __restrict__ mask) {
    extern __shared__ __half fsm[];
    uint32_t smbase = sptr(fsm);
    uint32_t qb = smbase;                               // Q: 64x64 halves, 8KB

    int tid = threadIdx.x, lane = tid & 31, wid = tid >> 5;
    int g = lane >> 2, tg = lane & 3;
    int bh = blockIdx.y, b = bh >> 4, h = bh & 15;
    int qt = blockIdx.x;

    const __half* Qp = g_Qh + (size_t)bh * SEQ * DK + (size_t)qt * 64 * DK;
    const __half* Kp = g_Kh + (size_t)bh * SEQ * DK;
    const __half* Vp = g_Vt + (size_t)bh * DK * SEQ;
    const unsigned char* Mp = mask + (size_t)b * SEQ * SEQ + (size_t)(qt * 64) * SEQ;
    int anyMask = g_maskAny;

    int aro = lane & 15,                       ako8 = (lane >> 4);
    int bro = ((lane >> 4) << 3) + (lane & 7), bko8 = ((lane >> 3) & 1);

    int rb[4], xt[4];
#pragma unroll
    for (int np = 0; np < 4; np++) rb[np] = (np * 16 + bro) * 128;
#pragma unroll
    for (int kk = 0; kk < 4; kk++) xt[kk] = swz_xt(bro & 7, kk, bko8);

    auto kvbase = [&](int st, int kv) { return smbase + 8192 + (st * 2 + kv) * 8192; };
    auto load_kv = [&](int it, int st) {
#pragma unroll
        for (int i = 0; i < 4; i++) {
            int cid = tid + i * 128, r = cid >> 3, c = cid & 7;
            uint32_t so = r * 128 + ((c ^ (r & 7)) << 4);
            cp16(kvbase(st, 0) + so, Kp + (size_t)it * 4096 + cid * 8);
            cp16(kvbase(st, 1) + so, Vp + (size_t)r * SEQ + it * 64 + c * 8);
        }
        cp_commit();
    };

    // prologue: {Q + KV0} group, then {KV1} group
#pragma unroll
    for (int i = 0; i < 4; i++) {
        int cid = tid + i * 128, r = cid >> 3, c = cid & 7;
        cp16(qb + r * 128 + ((c ^ (r & 7)) << 4), Qp + cid * 8);
    }
    load_kv(0, 0);
    load_kv(1, 1);

    cp_wait<1>(); __syncthreads();      // Q + KV0 ready

    unsigned qf[4][4];
#pragma unroll
    for (int kk = 0; kk < 4; kk++)
        ldsm4(qf[kk], swzb(qb, wid * 16 + aro, kk * 16 + ako8 * 8));

    float o[8][4] = {};
    float lacc[4] = {};
    float m0 = -1e30f, m1 = -1e30f;
    const unsigned ONES = 0x3C003C00u;

    for (int it = 0; it < SEQ / 64; it++) {
        if (it > 0) { cp_wait<1>(); __syncthreads(); }
        if (it + 2 < SEQ / 64) load_kv(it + 2, (it + 2) % 3);
        uint32_t kb = kvbase(it % 3, 0), vb = kvbase(it % 3, 1);

        // S = Q K^T  (exp2 domain: Q pre-scaled by 0.125*log2e)
        float s[8][4] = {};
#pragma unroll
        for (int kk = 0; kk < 4; kk++)
#pragma unroll
            for (int np = 0; np < 4; np++) {
                unsigned bf[4];
                ldsm4(bf, kb + rb[np] + xt[kk]);
                mma16816(s[np * 2],     qf[kk], bf[0], bf[1]);
                mma16816(s[np * 2 + 1], qf[kk], bf[2], bf[3]);
            }

        if (anyMask) {
            int r0 = wid * 16 + g;
            const unsigned char* M0 = Mp + (size_t)r0 * SEQ + it * 64;
            const unsigned char* M1 = M0 + 8 * SEQ;
#pragma unroll
            for (int j = 0; j < 8; j++) {
                int c = j * 8 + tg * 2;
                if (M0[c])     s[j][0] = -1e9f;
                if (M0[c + 1]) s[j][1] = -1e9f;
                if (M1[c])     s[j][2] = -1e9f;
                if (M1[c + 1]) s[j][3] = -1e9f;
            }
        }

        // online softmax (log2 domain) — in-thread max3 tree + 2 shuffles (exact)
        float rm0, rm1;
        {
            float t0 = fmax3(s[0][0], s[0][1], s[1][0]);
            float t1 = fmax3(s[1][1], s[2][0], s[2][1]);
            float t2 = fmax3(s[3][0], s[3][1], s[4][0]);
            float t3 = fmax3(s[4][1], s[5][0], s[5][1]);
            float t4 = fmax3(s[6][0], s[6][1], s[7][0]);
            rm0 = fmax3(fmax3(t0, t1, t2), fmax3(t3, t4, s[7][1]), -1e30f);
            float u0 = fmax3(s[0][2], s[0][3], s[1][2]);
            float u1 = fmax3(s[1][3], s[2][2], s[2][3]);
            float u2 = fmax3(s[3][2], s[3][3], s[4][2]);
            float u3 = fmax3(s[4][3], s[5][2], s[5][3]);
            float u4 = fmax3(s[6][2], s[6][3], s[7][2]);
            rm1 = fmax3(fmax3(u0, u1, u2), fmax3(u3, u4, s[7][3]), -1e30f);
        }
        rm0 = fmaxf(rm0, __shfl_xor_sync(0xffffffffu, rm0, 1));
        rm0 = fmaxf(rm0, __shfl_xor_sync(0xffffffffu, rm0, 2));
        rm1 = fmaxf(rm1, __shfl_xor_sync(0xffffffffu, rm1, 1));
        rm1 = fmaxf(rm1, __shfl_xor_sync(0xffffffffu, rm1, 2));
        float nm0 = fmaxf(m0, rm0), nm1 = fmaxf(m1, rm1);
        float a0 = exp2f(m0 - nm0), a1 = exp2f(m1 - nm1);
        m0 = nm0; m1 = nm1;
        // warp-uniform skip: rescale only when some row's max moved
        if (!__all_sync(0xffffffffu, (a0 == 1.0f) & (a1 == 1.0f))) {
#pragma unroll
            for (int j = 0; j < 8; j++) {
                o[j][0] *= a0; o[j][1] *= a0;
                o[j][2] *= a1; o[j][3] *= a1;
            }
            lacc[0] *= a0; lacc[1] *= a0; lacc[2] *= a1; lacc[3] *= a1;
        }

        // P = 2^(s-nm) as fp16 fragments, straight from score regs
        unsigned pf[4][4];
#pragma unroll
        for (int t = 0; t < 4; t++) {
            pf[t][0] = h2exp2_(packh2(s[2*t][0]   - nm0, s[2*t][1]   - nm0));
            pf[t][1] = h2exp2_(packh2(s[2*t][2]   - nm1, s[2*t][3]   - nm1));
            pf[t][2] = h2exp2_(packh2(s[2*t+1][0] - nm0, s[2*t+1][1] - nm0));
            pf[t][3] = h2exp2_(packh2(s[2*t+1][2] - nm1, s[2*t+1][3] - nm1));
        }
#pragma unroll
        for (int t = 0; t < 4; t++)
            mma16816(lacc, pf[t], ONES, ONES);      // exact f32 row sums of P

        // O += P V   (V tile is [d][key] -> n=d, k=keys)
#pragma unroll
        for (int t = 0; t < 4; t++)
#pragma unroll
            for (int np = 0; np < 4; np++) {
                unsigned bf[4];
                ldsm4(bf, vb + rb[np] + xt[t]);
                mma16816(o[np * 2],     pf[t], bf[0], bf[1]);
                mma16816(o[np * 2 + 1], pf[t], bf[2], bf[3]);
            }
    }

    float inv0 = 1.f / lacc[0], inv1 = 1.f / lacc[2];
    int srow = qt * 64 + wid * 16 + g;
#pragma unroll
    for (int j = 0; j < 8; j++) {
        int c = h * 64 + j * 8 + tg * 2;
        *(__half2*)(g_attn + (size_t)(b * SEQ + srow) * HID + c) =
            __floats2half2_rn(o[j][0] * inv0, o[j][1] * inv0);
        *(__half2*)(g_attn + (size_t)(b * SEQ + srow + 8) * HID + c) =
            __floats2half2_rn(o[j][2] * inv1, o[j][3] * inv1);
    }
}

// ---------------- launch -----------------------------------------------------
extern "C" void kernel_launch(void* const* d_in, const int* in_sizes, int n_in,
                              void* d_out, int out_size) {
    (void)in_sizes; (void)n_in; (void)out_size;
    const float* q = (const float*)d_in[0];
    const float* k = (const float*)d_in[1];
    const float* v = (const float*)d_in[2];
    const unsigned char* mask = (const unsigned char*)d_in[3];
    const float* Wq = (const float*)d_in[4];
    const float* Wk = (const float*)d_in[5];
    const float* Wv = (const float*)d_in[6];
    const float* Wo = (const float*)d_in[7];
    float* out = (float*)d_out;

    const int GSM = 2 * 24576;          // 48 KB -> 4 CTAs/SM
    const int FSM = 8192 + 3 * 16384;   // 56 KB -> 4 CTAs/SM
    static bool done = false;
    if (!done) {
        cudaFuncSetAttribute(gemm64, cudaFuncAttributeMaxDynamicSharedMemorySize, GSM);
        cudaFuncSetAttribute(flash,  cudaFuncAttributeMaxDynamicSharedMemorySize, FSM);
        done = true;
    }

    cvt18<<<dim3(1024, 18), 256>>>(q, k, v, Wq, Wk, Wv, Wo, (const uint4*)mask);

    gemm64<<<dim3(8, 64, 3), 128, GSM>>>(0, nullptr);    // fused Q,K,V projections

    flash<<<dim3(SEQ / 64, BATCH * HEADS), 128, FSM>>>(mask);

    gemm64<<<dim3(8, 64, 1), 128, GSM>>>(3, out);        // output projection
}